// round 1
// baseline (speedup 1.0000x reference)
#include <cuda_runtime.h>

// GHM loss, fused single pass:
//   pass kernel: per-element g=|x-t|, bin=floor(g*9.9999), loss=BCE(x,t);
//                accumulate per-bin loss-sum and count.
//   final kernel: beta_b = N / max(count_b * nonempty, 1); out = sum_b S_b*beta_b / N.

#define BINS 10
#define NTOT (16384LL * 2048LL)

__device__ double        g_loss_sum[BINS];
__device__ unsigned long long g_cnt[BINS];

__global__ void ghm_zero_kernel() {
    int t = threadIdx.x;
    if (t < BINS) {
        g_loss_sum[t] = 0.0;
        g_cnt[t] = 0ull;
    }
}

__global__ void __launch_bounds__(256) ghm_pass_kernel(
    const float4* __restrict__ x4,
    const float4* __restrict__ t4,
    int n4)
{
    float ls[BINS];
    int   cs[BINS];
#pragma unroll
    for (int b = 0; b < BINS; b++) { ls[b] = 0.0f; cs[b] = 0; }

    const int stride = gridDim.x * blockDim.x;
    for (int i = blockIdx.x * blockDim.x + threadIdx.x; i < n4; i += stride) {
        float4 xv = x4[i];
        float4 tv = t4[i];
#pragma unroll
        for (int c = 0; c < 4; c++) {
            float xx = (c == 0) ? xv.x : (c == 1) ? xv.y : (c == 2) ? xv.z : xv.w;
            float tt = (c == 0) ? tv.x : (c == 1) ? tv.y : (c == 2) ? tv.z : tv.w;
            float g = fabsf(xx - tt);
            int b = (int)(g * (10.0f - 1e-4f));   // floor, g >= 0
            b = (b > BINS - 1) ? (BINS - 1) : b;
            // BCE on probabilities: -(t*log(x) + (1-t)*log(1-x))
            float l = -(tt * __logf(xx) + (1.0f - tt) * __logf(1.0f - xx));
            ls[b] += l;
            cs[b] += 1;
        }
    }

    // warp-level reduction per bin
#pragma unroll
    for (int b = 0; b < BINS; b++) {
#pragma unroll
        for (int o = 16; o > 0; o >>= 1) {
            ls[b] += __shfl_down_sync(0xffffffffu, ls[b], o);
            cs[b] += __shfl_down_sync(0xffffffffu, cs[b], o);
        }
    }

    __shared__ float s_ls[BINS];
    __shared__ int   s_cs[BINS];
    if (threadIdx.x < BINS) { s_ls[threadIdx.x] = 0.0f; s_cs[threadIdx.x] = 0; }
    __syncthreads();

    if ((threadIdx.x & 31) == 0) {
#pragma unroll
        for (int b = 0; b < BINS; b++) {
            atomicAdd(&s_ls[b], ls[b]);
            atomicAdd(&s_cs[b], cs[b]);
        }
    }
    __syncthreads();

    if (threadIdx.x < BINS) {
        atomicAdd(&g_loss_sum[threadIdx.x], (double)s_ls[threadIdx.x]);
        atomicAdd(&g_cnt[threadIdx.x], (unsigned long long)s_cs[threadIdx.x]);
    }
}

__global__ void ghm_final_kernel(float* __restrict__ out)
{
    if (threadIdx.x == 0 && blockIdx.x == 0) {
        const double N = (double)NTOT;
        int nonempty = 0;
#pragma unroll
        for (int b = 0; b < BINS; b++) nonempty += (g_cnt[b] > 0ull) ? 1 : 0;
        double total = 0.0;
#pragma unroll
        for (int b = 0; b < BINS; b++) {
            double gd = (double)g_cnt[b] * (double)nonempty;
            if (gd < 1.0) gd = 1.0;
            double beta = N / gd;
            total += g_loss_sum[b] * beta;
        }
        out[0] = (float)(total / N);
    }
}

extern "C" void kernel_launch(void* const* d_in, const int* in_sizes, int n_in,
                              void* d_out, int out_size)
{
    const float4* x4 = (const float4*)d_in[0];
    const float4* t4 = (const float4*)d_in[1];
    float* out = (float*)d_out;

    const int n4 = (int)(NTOT / 4);   // 8388608 float4s per tensor

    ghm_zero_kernel<<<1, 32>>>();

    const int threads = 256;
    const int blocks = 148 * 8;       // grid-stride; ~27 float4 pairs per thread
    ghm_pass_kernel<<<blocks, threads>>>(x4, t4, n4);

    ghm_final_kernel<<<1, 32>>>(out);
}

// round 2
// speedup vs baseline: 3.8545x; 3.8545x over previous
#include <cuda_runtime.h>

// GHM loss, one pass over x/target (268 MB), HBM-bound design.
// Per-element: g=|x-t|, bin=floor(g*9.9999) (g<1 so bin<=9 always, no clamp),
// loss=BCE(x,t). Accumulate {loss,count} per bin in a transposed smem
// histogram hist[bin][tid] (bank-conflict-free, no atomics, no local-mem
// spills). Block reduces to global double accumulators (8 spread copies to
// avoid single-address atomic serialization); finalize computes beta and the
// mean, then re-zeros the accumulators for the next graph replay.

#define BINS 10
#define NTOT (16384LL * 2048LL)
#define NCOPY 8
#define TPB 256

__device__ double g_ls[NCOPY][BINS];   // zero-init at module load
__device__ double g_cs[NCOPY][BINS];

__global__ void __launch_bounds__(TPB) ghm_pass_kernel(
    const float4* __restrict__ x4,
    const float4* __restrict__ t4,
    int n4)
{
    // [bin][tid] float2 {loss_sum, count}; lane always hits its own bank.
    __shared__ float2 hist[BINS * TPB];

    const int tid = threadIdx.x;

    // zero smem histogram
#pragma unroll
    for (int b = 0; b < BINS; b++)
        hist[b * TPB + tid] = make_float2(0.0f, 0.0f);
    __syncthreads();

    const int stride = gridDim.x * blockDim.x;
    int i = blockIdx.x * blockDim.x + tid;

    for (; i < n4; i += stride) {
        float4 xv = x4[i];
        float4 tv = t4[i];
        float xs[4] = {xv.x, xv.y, xv.z, xv.w};
        float ts[4] = {tv.x, tv.y, tv.z, tv.w};
#pragma unroll
        for (int c = 0; c < 4; c++) {
            float xx = xs[c];
            float tt = ts[c];
            float g  = fabsf(xx - tt);
            int bin  = (int)(g * (10.0f - 1e-4f));   // g < 1 -> bin in [0,9]
            // loss = -(t*log(x) + (1-t)*log(1-x)) = -(t*(a-b) + b)
            float a  = __logf(xx);
            float b2 = __logf(1.0f - xx);
            float nl = fmaf(tt, a - b2, b2);          // = -loss
            float2* p = &hist[bin * TPB + tid];
            float2 v = *p;
            v.x -= nl;       // += loss
            v.y += 1.0f;     // count
            *p = v;
        }
    }
    __syncthreads();

    // block reduction: warp w handles bins w, w+8
    const int wid = tid >> 5;
    const int lid = tid & 31;
    for (int bin = wid; bin < BINS; bin += (TPB >> 5)) {
        double ls = 0.0, cs = 0.0;
#pragma unroll
        for (int k = 0; k < TPB / 32; k++) {
            float2 v = hist[bin * TPB + k * 32 + lid];
            ls += (double)v.x;
            cs += (double)v.y;
        }
#pragma unroll
        for (int o = 16; o > 0; o >>= 1) {
            ls += __shfl_down_sync(0xffffffffu, ls, o);
            cs += __shfl_down_sync(0xffffffffu, cs, o);
        }
        if (lid == 0) {
            int cp = blockIdx.x & (NCOPY - 1);
            atomicAdd(&g_ls[cp][bin], ls);
            atomicAdd(&g_cs[cp][bin], cs);
        }
    }
}

__global__ void ghm_final_kernel(float* __restrict__ out)
{
    __shared__ double s_ls[BINS], s_cs[BINS];
    int t = threadIdx.x;

    if (t < BINS) {
        double a = 0.0, c = 0.0;
#pragma unroll
        for (int k = 0; k < NCOPY; k++) { a += g_ls[k][t]; c += g_cs[k][t]; }
        s_ls[t] = a;
        s_cs[t] = c;
    }
    __syncthreads();

    if (t == 0) {
        const double N = (double)NTOT;
        int nonempty = 0;
#pragma unroll
        for (int b = 0; b < BINS; b++) nonempty += (s_cs[b] > 0.0) ? 1 : 0;
        double total = 0.0;
#pragma unroll
        for (int b = 0; b < BINS; b++) {
            double gd = s_cs[b] * (double)nonempty;
            if (gd < 1.0) gd = 1.0;
            total += s_ls[b] * (N / gd);
        }
        out[0] = (float)(total / N);
    }
    __syncthreads();

    // self-clean for the next graph replay (call 1 relies on static zero-init)
    if (t < NCOPY * BINS) {
        g_ls[t / BINS][t % BINS] = 0.0;
        g_cs[t / BINS][t % BINS] = 0.0;
    }
}

extern "C" void kernel_launch(void* const* d_in, const int* in_sizes, int n_in,
                              void* d_out, int out_size)
{
    const float4* x4 = (const float4*)d_in[0];
    const float4* t4 = (const float4*)d_in[1];
    float* out = (float*)d_out;

    const int n4 = (int)(NTOT / 4);   // 8388608 float4s per tensor

    ghm_pass_kernel<<<148 * 8, TPB>>>(x4, t4, n4);
    ghm_final_kernel<<<1, NCOPY * BINS>>>(out);
}

// round 3
// speedup vs baseline: 4.7160x; 1.2235x over previous
#include <cuda_runtime.h>

// GHM loss — single fused kernel, one pass over x/target (268 MB).
// Per element: g=|x-t|, bin=floor(g*9.9999), loss=BCE(x,t).
//  - loss accumulated (in log2 units) in transposed smem hist[bin][tid] (LDS.32/STS.32, conflict-free)
//  - count accumulated in a packed per-thread 64-bit register (10 bins x 6 bits; max 32 elems/thread)
// Block reduces to spread global double accumulators; the LAST block to finish
// (threadfence + atomic counter) computes beta / final mean, writes out, and
// resets the accumulators for the next graph replay.

#define BINS   10
#define TPB    256
#define BLOCKS 4096
#define ITERS  8                      // 4096*256*8 float4s = 2^23 exactly
#define NCOPY  32
#define NTOT   (16384LL * 2048LL)

__device__ double             g_ls[NCOPY][BINS];   // zero-init at module load
__device__ unsigned long long g_cs[NCOPY][BINS];
__device__ unsigned int       g_done;

__device__ __forceinline__ void proc(float xx, float tt,
                                     float* hist, int tid,
                                     unsigned long long& cnt)
{
    float g   = fabsf(xx - tt);
    int   bin = (int)(g * 9.9999f);          // g < 1 -> bin in [0,9]
    cnt += 1ull << (bin * 6);
    float a   = __log2f(xx);
    float b   = __log2f(1.0f - xx);
    float nl2 = fmaf(tt, a - b, b);          // = -(loss)/ln2
    float* p  = &hist[bin * TPB + tid];
    *p = *p - nl2;                           // += loss (log2 units)
}

__global__ void __launch_bounds__(TPB) ghm_kernel(
    const float4* __restrict__ x4,
    const float4* __restrict__ t4,
    float* __restrict__ out)
{
    __shared__ float hist[BINS * TPB];            // 10 KB
    __shared__ unsigned long long cpack[TPB];     // 2 KB
    __shared__ double s_ls[BINS], s_cs[BINS];
    __shared__ int s_last;

    const int tid = threadIdx.x;

#pragma unroll
    for (int b = 0; b < BINS; b++) hist[b * TPB + tid] = 0.0f;
    __syncthreads();

    unsigned long long cnt = 0ull;
    int idx = blockIdx.x * TPB + tid;
    const int stride = TPB * BLOCKS;

#pragma unroll
    for (int it = 0; it < ITERS; it++, idx += stride) {
        float4 xv = __ldcs(&x4[idx]);
        float4 tv = __ldcs(&t4[idx]);
        proc(xv.x, tv.x, hist, tid, cnt);
        proc(xv.y, tv.y, hist, tid, cnt);
        proc(xv.z, tv.z, hist, tid, cnt);
        proc(xv.w, tv.w, hist, tid, cnt);
    }

    cpack[tid] = cnt;
    __syncthreads();

    // block reduction: warp w handles bins w and w+8
    const int wid = tid >> 5;
    const int lid = tid & 31;
    const int cp  = blockIdx.x & (NCOPY - 1);
    for (int bin = wid; bin < BINS; bin += 8) {
        float ls = 0.0f;
        unsigned c = 0;
#pragma unroll
        for (int k = 0; k < TPB / 32; k++) {
            ls += hist[bin * TPB + k * 32 + lid];
            c  += (unsigned)((cpack[k * 32 + lid] >> (6 * bin)) & 63ull);
        }
#pragma unroll
        for (int o = 16; o > 0; o >>= 1)
            ls += __shfl_down_sync(0xffffffffu, ls, o);
        c = __reduce_add_sync(0xffffffffu, c);
        if (lid == 0) {
            atomicAdd(&g_ls[cp][bin], (double)ls);
            atomicAdd(&g_cs[cp][bin], (unsigned long long)c);
        }
    }

    // ---- last-block finalize ----
    if (tid == 0) {
        __threadfence();
        unsigned old = atomicAdd(&g_done, 1u);
        s_last = (old == (unsigned)(BLOCKS - 1)) ? 1 : 0;
    }
    __syncthreads();
    if (!s_last) return;

    if (tid < BINS) {
        double a = 0.0;
        unsigned long long c = 0ull;
#pragma unroll
        for (int k = 0; k < NCOPY; k++) {
            a += ((volatile double*)&g_ls[k][tid])[0];
            c += ((volatile unsigned long long*)&g_cs[k][tid])[0];
        }
        s_ls[tid] = a;
        s_cs[tid] = (double)c;
    }
    __syncthreads();

    if (tid == 0) {
        const double N = (double)NTOT;
        int ne = 0;
#pragma unroll
        for (int b = 0; b < BINS; b++) ne += (s_cs[b] > 0.0) ? 1 : 0;
        double tot = 0.0;
#pragma unroll
        for (int b = 0; b < BINS; b++) {
            double gd = s_cs[b] * (double)ne;
            if (gd < 1.0) gd = 1.0;
            tot += s_ls[b] * (N / gd);
        }
        out[0] = (float)(tot * 0.6931471805599453 / N);   // ln2: log2 -> ln
    }
    __syncthreads();   // reads of g_ls/g_cs complete before reset

    for (int i = tid; i < NCOPY * BINS; i += TPB) {
        g_ls[i / BINS][i % BINS] = 0.0;
        g_cs[i / BINS][i % BINS] = 0ull;
    }
    if (tid == 0) g_done = 0u;
}

extern "C" void kernel_launch(void* const* d_in, const int* in_sizes, int n_in,
                              void* d_out, int out_size)
{
    const float4* x4 = (const float4*)d_in[0];
    const float4* t4 = (const float4*)d_in[1];
    float* out = (float*)d_out;

    ghm_kernel<<<BLOCKS, TPB>>>(x4, t4, out);
}

// round 4
// speedup vs baseline: 5.1767x; 1.0977x over previous
#include <cuda_runtime.h>

// GHM loss — single fused kernel, one pass over x/target (268 MB).
// Per element: g=|x-t|, bin=floor(g*9.9999), loss=BCE(x,t) in log2 units.
// Count and loss share ONE smem accumulator per (bin,thread):
//   v += K - nl2   where K=16384, nl2 = -(loss)/ln2  (so v = count*K + loss_sum)
// count <= 32 per thread-bin -> v <= 2^19 + 426; count recovered exactly via
// rintf(v/K); loss residual error ~3e-5 relative (fp32 ulp at 2^19 = 1/16).
// Last block (threadfence + counter) finalizes beta, writes mean, resets state.

#define BINS   10
#define TPB    256
#define BLOCKS 4096
#define ITERS  8                      // 4096*256*8 float4s = 2^23 exactly
#define NCOPY  32
#define NTOT   (16384LL * 2048LL)
#define KOFF   16384.0f

__device__ double             g_ls[NCOPY][BINS];   // zero-init at module load
__device__ unsigned long long g_cs[NCOPY][BINS];
__device__ unsigned int       g_done;

__device__ __forceinline__ void proc(float xx, float tt, float* hist, int tid)
{
    float g   = fabsf(xx - tt);
    int   bin = (int)(g * 9.9999f);          // g < 1 -> bin in [0,9]
    float a   = __log2f(xx);
    float b   = __log2f(1.0f - xx);
    // K - nl2 = K - (t*(a-b) + b) = fma(t, b-a, K-b)
    float add = fmaf(tt, b - a, KOFF - b);
    float* p  = &hist[bin * TPB + tid];
    *p = *p + add;
}

__global__ void __launch_bounds__(TPB, 6) ghm_kernel(
    const float4* __restrict__ x4,
    const float4* __restrict__ t4,
    float* __restrict__ out)
{
    __shared__ float hist[BINS * TPB];            // 10 KB
    __shared__ double s_ls[BINS], s_cs[BINS];
    __shared__ int s_last;

    const int tid = threadIdx.x;

#pragma unroll
    for (int b = 0; b < BINS; b++) hist[b * TPB + tid] = 0.0f;
    __syncthreads();

    const int stride = TPB * BLOCKS;
    int idx = blockIdx.x * TPB + tid;

    float4 xa = __ldcs(&x4[idx]);
    float4 ta = __ldcs(&t4[idx]);

#pragma unroll
    for (int it = 0; it < ITERS; it++) {
        float4 xb, tb;
        if (it + 1 < ITERS) {
            xb = __ldcs(&x4[idx + stride]);
            tb = __ldcs(&t4[idx + stride]);
        }
        proc(xa.x, ta.x, hist, tid);
        proc(xa.y, ta.y, hist, tid);
        proc(xa.z, ta.z, hist, tid);
        proc(xa.w, ta.w, hist, tid);
        xa = xb; ta = tb;
        idx += stride;
    }
    __syncthreads();

    // block reduction: warp w handles bins w and w+8
    const int wid = tid >> 5;
    const int lid = tid & 31;
    const int cp  = blockIdx.x & (NCOPY - 1);
    for (int bin = wid; bin < BINS; bin += 8) {
        float ls = 0.0f;
        int   c  = 0;
#pragma unroll
        for (int k = 0; k < TPB / 32; k++) {
            float v  = hist[bin * TPB + k * 32 + lid];
            int   ci = __float2int_rn(v * (1.0f / KOFF));
            ls += v - (float)ci * KOFF;
            c  += ci;
        }
#pragma unroll
        for (int o = 16; o > 0; o >>= 1) {
            ls += __shfl_down_sync(0xffffffffu, ls, o);
            c  += __shfl_down_sync(0xffffffffu, c, o);
        }
        if (lid == 0) {
            atomicAdd(&g_ls[cp][bin], (double)ls);
            atomicAdd(&g_cs[cp][bin], (unsigned long long)c);
        }
    }

    // ---- last-block finalize ----
    if (tid == 0) {
        __threadfence();
        unsigned old = atomicAdd(&g_done, 1u);
        s_last = (old == (unsigned)(BLOCKS - 1)) ? 1 : 0;
    }
    __syncthreads();
    if (!s_last) return;

    if (tid < BINS) {
        double a = 0.0;
        unsigned long long c = 0ull;
#pragma unroll
        for (int k = 0; k < NCOPY; k++) {
            a += ((volatile double*)&g_ls[k][tid])[0];
            c += ((volatile unsigned long long*)&g_cs[k][tid])[0];
        }
        s_ls[tid] = a;
        s_cs[tid] = (double)c;
    }
    __syncthreads();

    if (tid == 0) {
        const double N = (double)NTOT;
        int ne = 0;
#pragma unroll
        for (int b = 0; b < BINS; b++) ne += (s_cs[b] > 0.0) ? 1 : 0;
        double tot = 0.0;
#pragma unroll
        for (int b = 0; b < BINS; b++) {
            double gd = s_cs[b] * (double)ne;
            if (gd < 1.0) gd = 1.0;
            tot += s_ls[b] * (N / gd);
        }
        out[0] = (float)(tot * 0.6931471805599453 / N);   // log2 -> ln
    }
    __syncthreads();   // reads of g_ls/g_cs complete before reset

    for (int i = tid; i < NCOPY * BINS; i += TPB) {
        g_ls[i / BINS][i % BINS] = 0.0;
        g_cs[i / BINS][i % BINS] = 0ull;
    }
    if (tid == 0) g_done = 0u;
}

extern "C" void kernel_launch(void* const* d_in, const int* in_sizes, int n_in,
                              void* d_out, int out_size)
{
    const float4* x4 = (const float4*)d_in[0];
    const float4* t4 = (const float4*)d_in[1];
    float* out = (float*)d_out;

    ghm_kernel<<<BLOCKS, TPB>>>(x4, t4, out);
}

// round 5
// speedup vs baseline: 5.2458x; 1.0133x over previous
#include <cuda_runtime.h>

// GHM loss — single fused kernel, one pass over x/target (268 MB).
// Per element: g=|x-t|, bin=floor(g*9.9999), loss=BCE(x,t) in log2 units.
// Count and loss share ONE smem accumulator per (bin,thread):
//   v += K - nl2, K=16384 -> v = count*K + loss_sum (count<=32, loss<=426)
// count recovered exactly via rintf(v/K). Occupancy-first build: no manual
// prefetch, __launch_bounds__(256,8) caps regs at 32 -> 2048 thr/SM.
// Last block (threadfence + counter) finalizes beta, writes mean, resets state.

#define BINS   10
#define TPB    256
#define BLOCKS 4096
#define ITERS  8                      // 4096*256*8 float4s = 2^23 exactly
#define NCOPY  32
#define NTOT   (16384LL * 2048LL)
#define KOFF   16384.0f

__device__ double             g_ls[NCOPY][BINS];   // zero-init at module load
__device__ unsigned long long g_cs[NCOPY][BINS];
__device__ unsigned int       g_done;

__device__ __forceinline__ void proc(float xx, float tt, float* __restrict__ h)
{
    float g   = fabsf(xx - tt);
    int   bin = (int)(g * 9.9999f);          // g < 1 -> bin in [0,9]
    float a   = __log2f(xx);
    float b   = __log2f(1.0f - xx);
    float add = fmaf(tt, b - a, KOFF - b);   // K - (-loss/ln2)
    h[bin * TPB] += add;
}

__global__ void __launch_bounds__(TPB, 8) ghm_kernel(
    const float4* __restrict__ x4,
    const float4* __restrict__ t4,
    float* __restrict__ out)
{
    __shared__ float hist[BINS * TPB];            // 10 KB
    __shared__ double s_ls[BINS], s_cs[BINS];
    __shared__ int s_last;

    const int tid = threadIdx.x;
    float* __restrict__ h = &hist[tid];

#pragma unroll
    for (int b = 0; b < BINS; b++) h[b * TPB] = 0.0f;
    __syncthreads();

    const int stride = TPB * BLOCKS;
    int idx = blockIdx.x * TPB + tid;

#pragma unroll
    for (int it = 0; it < ITERS; it++, idx += stride) {
        float4 xv = __ldcs(&x4[idx]);
        float4 tv = __ldcs(&t4[idx]);
        proc(xv.x, tv.x, h);
        proc(xv.y, tv.y, h);
        proc(xv.z, tv.z, h);
        proc(xv.w, tv.w, h);
    }
    __syncthreads();

    // block reduction: warp w handles bins w and w+8
    const int wid = tid >> 5;
    const int lid = tid & 31;
    const int cp  = blockIdx.x & (NCOPY - 1);
    for (int bin = wid; bin < BINS; bin += 8) {
        float ls = 0.0f;
        int   c  = 0;
#pragma unroll
        for (int k = 0; k < TPB / 32; k++) {
            float v  = hist[bin * TPB + k * 32 + lid];
            int   ci = __float2int_rn(v * (1.0f / KOFF));
            ls += v - (float)ci * KOFF;
            c  += ci;
        }
#pragma unroll
        for (int o = 16; o > 0; o >>= 1) {
            ls += __shfl_down_sync(0xffffffffu, ls, o);
            c  += __shfl_down_sync(0xffffffffu, c, o);
        }
        if (lid == 0) {
            atomicAdd(&g_ls[cp][bin], (double)ls);
            atomicAdd(&g_cs[cp][bin], (unsigned long long)c);
        }
    }

    // ---- last-block finalize ----
    if (tid == 0) {
        __threadfence();
        unsigned old = atomicAdd(&g_done, 1u);
        s_last = (old == (unsigned)(BLOCKS - 1)) ? 1 : 0;
    }
    __syncthreads();
    if (!s_last) return;

    if (tid < BINS) {
        double a = 0.0;
        unsigned long long c = 0ull;
#pragma unroll
        for (int k = 0; k < NCOPY; k++) {
            a += ((volatile double*)&g_ls[k][tid])[0];
            c += ((volatile unsigned long long*)&g_cs[k][tid])[0];
        }
        s_ls[tid] = a;
        s_cs[tid] = (double)c;
    }
    __syncthreads();

    if (tid == 0) {
        const double N = (double)NTOT;
        int ne = 0;
#pragma unroll
        for (int b = 0; b < BINS; b++) ne += (s_cs[b] > 0.0) ? 1 : 0;
        double tot = 0.0;
#pragma unroll
        for (int b = 0; b < BINS; b++) {
            double gd = s_cs[b] * (double)ne;
            if (gd < 1.0) gd = 1.0;
            tot += s_ls[b] * (N / gd);
        }
        out[0] = (float)(tot * 0.6931471805599453 / N);   // log2 -> ln
    }
    __syncthreads();   // reads of g_ls/g_cs complete before reset

    for (int i = tid; i < NCOPY * BINS; i += TPB) {
        g_ls[i / BINS][i % BINS] = 0.0;
        g_cs[i / BINS][i % BINS] = 0ull;
    }
    if (tid == 0) g_done = 0u;
}

extern "C" void kernel_launch(void* const* d_in, const int* in_sizes, int n_in,
                              void* d_out, int out_size)
{
    const float4* x4 = (const float4*)d_in[0];
    const float4* t4 = (const float4*)d_in[1];
    float* out = (float*)d_out;

    ghm_kernel<<<BLOCKS, TPB>>>(x4, t4, out);
}